// round 1
// baseline (speedup 1.0000x reference)
#include <cuda_runtime.h>
#include <math.h>

#define BB   1024
#define NN   40
#define ETAD 64
#define KK   32
#define ZDIM 32
#define NA   10
#define NB   5
#define CH   128
#define AH   128
#define BH   64
#define NODES (BB*NN)        /* 40960 */
#define EPB   780            /* C(40,2) edges per batch */

/* ---- scratch (static device memory; allocation-free) ---- */
__device__ float g_s[BB*KK];           /* pre-softmax cluster logits */
__device__ float g_z[NODES*ZDIM];      /* latent z per node          */
__device__ float g_wsym[NB*ZDIM*ZDIM]; /* symmetrized bond matrices  */

/* ---------------- kernel 0: Wsym = 0.5*(W + W^T) ---------------- */
__global__ void k_wsym(const float* __restrict__ bm) {
    int i = blockIdx.x * blockDim.x + threadIdx.x;
    if (i < NB*ZDIM*ZDIM) {
        int t = i / (ZDIM*ZDIM);
        int r = (i / ZDIM) % ZDIM;
        int c = i % ZDIM;
        g_wsym[i] = 0.5f * (bm[t*ZDIM*ZDIM + r*ZDIM + c] +
                            bm[t*ZDIM*ZDIM + c*ZDIM + r]);
    }
}

/* -------- kernel 1: per-batch cluster resblock logits s[b,k] -------- */
__global__ void k_cluster(const float* __restrict__ eta,
                          const float* __restrict__ cW1, const float* __restrict__ cb1,
                          const float* __restrict__ cW2, const float* __restrict__ cb2,
                          const float* __restrict__ cWs, const float* __restrict__ cbs) {
    __shared__ float eta_sm[ETAD];
    __shared__ float h_sm[CH];
    int b = blockIdx.x;
    int t = threadIdx.x;           /* 128 threads */
    if (t < ETAD) eta_sm[t] = eta[b*ETAD + t];
    __syncthreads();
    float acc = cb1[t];
    #pragma unroll 16
    for (int e = 0; e < ETAD; e++) acc = fmaf(eta_sm[e], cW1[e*CH + t], acc);
    h_sm[t] = fmaxf(acc, 0.f);
    __syncthreads();
    if (t < KK) {
        float s = cb2[t] + cbs[t];
        #pragma unroll 16
        for (int j = 0; j < CH; j++) s = fmaf(h_sm[j], cW2[j*KK + t], s);
        #pragma unroll 16
        for (int e = 0; e < ETAD; e++) s = fmaf(eta_sm[e], cWs[e*KK + t], s);
        g_s[b*KK + t] = s;
    }
}

/* -------- kernel 2: warp-per-node: argmax -> z -> atom MLP -------- */
__global__ __launch_bounds__(256)
void k_node(const float* __restrict__ gum, const float* __restrict__ zn,
            const float* __restrict__ cm,  const float* __restrict__ cls,
            const float* __restrict__ aW1, const float* __restrict__ ab1,
            const float* __restrict__ aW2, const float* __restrict__ ab2,
            const float* __restrict__ aWs, const float* __restrict__ absk,
            float* __restrict__ atom_out) {
    __shared__ float zsm[8][ZDIM];
    __shared__ float hsm[8][AH];
    int warp = threadIdx.x >> 5;
    int lane = threadIdx.x & 31;
    int node = blockIdx.x * 8 + warp;
    int b = node / NN;

    /* argmax_k ( s[b,k] + gumbel[node,k] )  — log-softmax shift dropped */
    float val = g_s[b*KK + lane] + gum[node*KK + lane];
    int idx = lane;
    #pragma unroll
    for (int off = 16; off; off >>= 1) {
        float ov = __shfl_xor_sync(0xffffffffu, val, off);
        int   oi = __shfl_xor_sync(0xffffffffu, idx, off);
        if (ov > val || (ov == val && oi < idx)) { val = ov; idx = oi; }
    }
    int kmax = idx;

    /* z = z_noise * exp(clip(log_sigma)) + mu */
    float ls = cls[kmax*ZDIM + lane];
    float sg = expf(fminf(fmaxf(ls, -20.f), 30.f));
    float z  = fmaf(zn[node*ZDIM + lane], sg, cm[kmax*ZDIM + lane]);
    g_z[node*ZDIM + lane] = z;
    zsm[warp][lane] = z;
    __syncwarp();

    /* hidden: 4 units per lane, float4 weight loads (coalesced) */
    float4 acc = reinterpret_cast<const float4*>(ab1)[lane];
    #pragma unroll
    for (int d = 0; d < ZDIM; d++) {
        float zd = zsm[warp][d];
        float4 w = reinterpret_cast<const float4*>(aW1)[d*32 + lane];
        acc.x = fmaf(zd, w.x, acc.x);
        acc.y = fmaf(zd, w.y, acc.y);
        acc.z = fmaf(zd, w.z, acc.z);
        acc.w = fmaf(zd, w.w, acc.w);
    }
    acc.x = fmaxf(acc.x, 0.f); acc.y = fmaxf(acc.y, 0.f);
    acc.z = fmaxf(acc.z, 0.f); acc.w = fmaxf(acc.w, 0.f);
    reinterpret_cast<float4*>(hsm[warp])[lane] = acc;
    __syncwarp();

    if (lane < NA) {
        float o = ab2[lane] + absk[lane];
        #pragma unroll 8
        for (int j = 0; j < AH; j++) o = fmaf(hsm[warp][j], aW2[j*NA + lane], o);
        #pragma unroll
        for (int d = 0; d < ZDIM; d++) o = fmaf(zsm[warp][d], aWs[d*NA + lane], o);
        atom_out[node*NA + lane] = o;
    }
}

/* -------- kernel 3: block-per-batch edge pipeline -------- */
__global__ __launch_bounds__(256)
void k_edge(const int* __restrict__ ei,
            const float* __restrict__ bW1, const float* __restrict__ bb1,
            const float* __restrict__ bW2, const float* __restrict__ bb2,
            const float* __restrict__ bWs, const float* __restrict__ bbs,
            float* __restrict__ edge_out) {
    __shared__ float zsm[NN*33];          /* [40][33] padded            */
    __shared__ float vsm[NB*ZDIM*NN];     /* [t][d][j] = 6400 floats    */
    __shared__ float w1s[NB*BH], w2s[BH*NB], wss[NB*NB];
    __shared__ float b1s[BH], b2s[NB], bss[NB];

    int b   = blockIdx.x;
    int tid = threadIdx.x;

    for (int i = tid; i < NB*BH; i += 256) { w1s[i] = bW1[i]; w2s[i] = bW2[i]; }
    if (tid < NB*NB) wss[tid] = bWs[tid];
    if (tid < BH)    b1s[tid] = bb1[tid];
    if (tid < NB)    { b2s[tid] = bb2[tid]; bss[tid] = bbs[tid]; }

    for (int i = tid; i < NN*ZDIM; i += 256) {
        int n = i >> 5, d = i & 31;
        zsm[n*33 + d] = g_z[(b*NN)*ZDIM + i];
    }
    __syncthreads();

    /* v[t][d][j] = sum_c Wsym[t][c][d] * z[j][c]   (Wsym symmetric) */
    for (int i = tid; i < NB*ZDIM*NN; i += 256) {
        int j  = i % NN;
        int td = i / NN;
        int t  = td >> 5, d = td & 31;
        const float* W = g_wsym + t*ZDIM*ZDIM + d;   /* stride ZDIM over c */
        float acc = 0.f;
        #pragma unroll
        for (int c = 0; c < ZDIM; c++) acc = fmaf(zsm[j*33 + c], W[c*ZDIM], acc);
        vsm[i] = acc;                                 /* i == t*1280 + d*40 + j */
    }
    __syncthreads();

    const int*  eib  = ei       + (size_t)b * EPB * 2;
    float*      outb = edge_out + (size_t)b * EPB * NB;

    for (int e = tid; e < EPB; e += 256) {
        int ii = eib[2*e]     - b*NN;
        int jj = eib[2*e + 1] - b*NN;

        float bil[NB] = {0.f, 0.f, 0.f, 0.f, 0.f};
        #pragma unroll
        for (int d = 0; d < ZDIM; d++) {
            float zd = zsm[ii*33 + d];
            int base = d*NN + jj;
            #pragma unroll
            for (int t = 0; t < NB; t++)
                bil[t] = fmaf(zd, vsm[t*ZDIM*NN + base], bil[t]);
        }

        float o[NB];
        #pragma unroll
        for (int t2 = 0; t2 < NB; t2++) {
            float acc = b2s[t2] + bss[t2];
            #pragma unroll
            for (int t = 0; t < NB; t++) acc = fmaf(bil[t], wss[t*NB + t2], acc);
            o[t2] = acc;
        }
        #pragma unroll 4
        for (int j = 0; j < BH; j++) {
            float hv = b1s[j];
            #pragma unroll
            for (int t = 0; t < NB; t++) hv = fmaf(bil[t], w1s[t*BH + j], hv);
            hv = fmaxf(hv, 0.f);
            #pragma unroll
            for (int t = 0; t < NB; t++) o[t] = fmaf(hv, w2s[j*NB + t], o[t]);
        }

        /* softmax over 5 */
        float m = o[0];
        #pragma unroll
        for (int t = 1; t < NB; t++) m = fmaxf(m, o[t]);
        float eo[NB], s = 0.f;
        #pragma unroll
        for (int t = 0; t < NB; t++) { eo[t] = expf(o[t] - m); s += eo[t]; }
        float inv = 1.f / s;
        #pragma unroll
        for (int t = 0; t < NB; t++) outb[e*NB + t] = eo[t] * inv;
    }
}

/* ------------------------- launch ------------------------- */
extern "C" void kernel_launch(void* const* d_in, const int* in_sizes, int n_in,
                              void* d_out, int out_size) {
    const float* eta  = (const float*)d_in[0];
    const float* gum  = (const float*)d_in[1];
    const float* zn   = (const float*)d_in[2];
    const float* cW1  = (const float*)d_in[3];
    const float* cb1  = (const float*)d_in[4];
    const float* cW2  = (const float*)d_in[5];
    const float* cb2  = (const float*)d_in[6];
    const float* cWs  = (const float*)d_in[7];
    const float* cbs  = (const float*)d_in[8];
    const float* cm   = (const float*)d_in[9];
    const float* cls  = (const float*)d_in[10];
    const float* aW1  = (const float*)d_in[11];
    const float* ab1  = (const float*)d_in[12];
    const float* aW2  = (const float*)d_in[13];
    const float* ab2  = (const float*)d_in[14];
    const float* aWs  = (const float*)d_in[15];
    const float* absk = (const float*)d_in[16];
    const float* bm   = (const float*)d_in[17];
    const float* bW1  = (const float*)d_in[18];
    const float* bb1  = (const float*)d_in[19];
    const float* bW2  = (const float*)d_in[20];
    const float* bb2  = (const float*)d_in[21];
    const float* bWs  = (const float*)d_in[22];
    const float* bbs  = (const float*)d_in[23];
    const int*   ei   = (const int*)  d_in[24];

    float* atom_out = (float*)d_out;                 /* [40960,10]  */
    float* edge_out = atom_out + (size_t)NODES * NA; /* [798720,5]  */

    k_wsym   <<<(NB*ZDIM*ZDIM + 255)/256, 256>>>(bm);
    k_cluster<<<BB, CH>>>(eta, cW1, cb1, cW2, cb2, cWs, cbs);
    k_node   <<<NODES/8, 256>>>(gum, zn, cm, cls, aW1, ab1, aW2, ab2, aWs, absk, atom_out);
    k_edge   <<<BB, 256>>>(ei, bW1, bb1, bW2, bb2, bWs, bbs, edge_out);
}

// round 4
// speedup vs baseline: 1.2780x; 1.2780x over previous
#include <cuda_runtime.h>
#include <math.h>

#define BB   1024
#define NN   40
#define ETAD 64
#define KK   32
#define ZDIM 32
#define NA   10
#define NB   5
#define CH   128
#define AH   128
#define BH   64
#define NODES (BB*NN)        /* 40960 */
#define EPB   780            /* C(40,2) edges per batch */
#define HPAIR 390            /* EPB/2 */
#define ZPAD  36             /* padded row stride (floats), 16B aligned, LDS.128 conflict-free */

/* ---- scratch (static device memory; allocation-free).
   __align__(16): accessed through float4 casts. ---- */
__device__ __align__(16) float g_s[BB*KK];           /* pre-softmax cluster logits */
__device__ __align__(16) float g_z[NODES*ZDIM];      /* latent z per node          */
__device__ __align__(16) float g_wsym[NB*ZDIM*ZDIM]; /* symmetrized bond matrices  */

/* ---- f32x2 packed helpers (sm_100+) ---- */
__device__ __forceinline__ unsigned long long pk2(float lo, float hi) {
    unsigned long long r;
    asm("mov.b64 %0, {%1, %2};" : "=l"(r) : "f"(lo), "f"(hi));
    return r;
}
__device__ __forceinline__ void upk2(unsigned long long v, float& lo, float& hi) {
    asm("mov.b64 {%0, %1}, %2;" : "=f"(lo), "=f"(hi) : "l"(v));
}
__device__ __forceinline__ unsigned long long fma2(unsigned long long a,
                                                   unsigned long long b,
                                                   unsigned long long c) {
    unsigned long long r;
    asm("fma.rn.f32x2 %0, %1, %2, %3;" : "=l"(r) : "l"(a), "l"(b), "l"(c));
    return r;
}

/* ---------------- kernel 0: Wsym = 0.5*(W + W^T) ---------------- */
__global__ void k_wsym(const float* __restrict__ bm) {
    int i = blockIdx.x * blockDim.x + threadIdx.x;
    if (i < NB*ZDIM*ZDIM) {
        int t = i / (ZDIM*ZDIM);
        int r = (i / ZDIM) % ZDIM;
        int c = i % ZDIM;
        g_wsym[i] = 0.5f * (bm[t*ZDIM*ZDIM + r*ZDIM + c] +
                            bm[t*ZDIM*ZDIM + c*ZDIM + r]);
    }
}

/* -------- kernel 1: per-batch cluster resblock logits s[b,k] -------- */
__global__ void k_cluster(const float* __restrict__ eta,
                          const float* __restrict__ cW1, const float* __restrict__ cb1,
                          const float* __restrict__ cW2, const float* __restrict__ cb2,
                          const float* __restrict__ cWs, const float* __restrict__ cbs) {
    __shared__ float eta_sm[ETAD];
    __shared__ float h_sm[CH];
    int b = blockIdx.x;
    int t = threadIdx.x;           /* 128 threads */
    if (t < ETAD) eta_sm[t] = eta[b*ETAD + t];
    __syncthreads();
    float acc = cb1[t];
    #pragma unroll 16
    for (int e = 0; e < ETAD; e++) acc = fmaf(eta_sm[e], cW1[e*CH + t], acc);
    h_sm[t] = fmaxf(acc, 0.f);
    __syncthreads();
    if (t < KK) {
        float s = cb2[t] + cbs[t];
        #pragma unroll 16
        for (int j = 0; j < CH; j++) s = fmaf(h_sm[j], cW2[j*KK + t], s);
        #pragma unroll 16
        for (int e = 0; e < ETAD; e++) s = fmaf(eta_sm[e], cWs[e*KK + t], s);
        g_s[b*KK + t] = s;
    }
}

/* -------- kernel 2: warp-per-node x4: argmax -> z -> atom MLP -------- */
/* 32 nodes per block (8 warps x 4 nodes) amortizes weight staging.     */
__global__ __launch_bounds__(256)
void k_node(const float* __restrict__ gum, const float* __restrict__ zn,
            const float* __restrict__ cm,  const float* __restrict__ cls,
            const float* __restrict__ aW1, const float* __restrict__ ab1,
            const float* __restrict__ aW2, const float* __restrict__ ab2,
            const float* __restrict__ aWs, const float* __restrict__ absk,
            float* __restrict__ atom_out) {
    __shared__ float4 w1s4[ZDIM*32];   /* aW1, [d][lane] float4 units: 16KB */
    __shared__ float  aw2s[AH*NA];     /* [j][o] 5KB   */
    __shared__ float  awss[ZDIM*NA];   /* [d][o] 1.25KB */
    __shared__ float4 ab1s4[32];
    __shared__ float  ab2s[NA];        /* ab2 + abs_   */
    /* zsm/hsm are float4-cast: MUST be 16B aligned (a bare float[] is only
       4B-aligned and its placement shifts with neighboring smem arrays). */
    __shared__ __align__(16) float  zsm[8][ZDIM];
    __shared__ __align__(16) float  hsm[8][AH];

    int tid  = threadIdx.x;
    int warp = tid >> 5;
    int lane = tid & 31;

    for (int i = tid; i < ZDIM*32; i += 256) w1s4[i] = ((const float4*)aW1)[i];
    for (int i = tid; i < AH*NA;  i += 256) aw2s[i]  = aW2[i];
    for (int i = tid; i < ZDIM*NA; i += 256) awss[i] = aWs[i];
    if (tid < 32) ab1s4[tid] = ((const float4*)ab1)[tid];
    if (tid < NA) ab2s[tid]  = ab2[tid] + absk[tid];
    __syncthreads();

    int node0 = blockIdx.x * 32 + warp;

    #pragma unroll
    for (int u = 0; u < 4; u++) {
        int node = node0 + u*8;
        int b = node / NN;

        /* argmax_k ( s[b,k] + gumbel[node,k] ) */
        float val = g_s[b*KK + lane] + gum[node*KK + lane];
        int idx = lane;
        #pragma unroll
        for (int off = 16; off; off >>= 1) {
            float ov = __shfl_xor_sync(0xffffffffu, val, off);
            int   oi = __shfl_xor_sync(0xffffffffu, idx, off);
            if (ov > val || (ov == val && oi < idx)) { val = ov; idx = oi; }
        }
        int kmax = idx;

        /* z = z_noise * exp(clip(log_sigma)) + mu */
        float ls = cls[kmax*ZDIM + lane];
        float sg = __expf(fminf(fmaxf(ls, -20.f), 30.f));
        float z  = fmaf(zn[node*ZDIM + lane], sg, cm[kmax*ZDIM + lane]);
        g_z[node*ZDIM + lane] = z;
        zsm[warp][lane] = z;
        __syncwarp();

        /* hidden: 4 units per lane */
        float4 acc = ab1s4[lane];
        #pragma unroll
        for (int d = 0; d < ZDIM; d++) {
            float zd = zsm[warp][d];
            float4 w = w1s4[d*32 + lane];
            acc.x = fmaf(zd, w.x, acc.x);
            acc.y = fmaf(zd, w.y, acc.y);
            acc.z = fmaf(zd, w.z, acc.z);
            acc.w = fmaf(zd, w.w, acc.w);
        }
        acc.x = fmaxf(acc.x, 0.f); acc.y = fmaxf(acc.y, 0.f);
        acc.z = fmaxf(acc.z, 0.f); acc.w = fmaxf(acc.w, 0.f);
        reinterpret_cast<float4*>(hsm[warp])[lane] = acc;
        __syncwarp();

        if (lane < NA) {
            float o = ab2s[lane];
            #pragma unroll 8
            for (int j = 0; j < AH; j++) o = fmaf(hsm[warp][j], aw2s[j*NA + lane], o);
            #pragma unroll
            for (int d = 0; d < ZDIM; d++) o = fmaf(zsm[warp][d], awss[d*NA + lane], o);
            atom_out[node*NA + lane] = o;
        }
        __syncwarp();
    }
}

/* -------- kernel 3: block-per-batch edge pipeline (f32x2 packed) -------- */
__global__ __launch_bounds__(256)
void k_edge(const int* __restrict__ ei,
            const float* __restrict__ bW1, const float* __restrict__ bb1,
            const float* __restrict__ bW2, const float* __restrict__ bb2,
            const float* __restrict__ bWs, const float* __restrict__ bbs,
            float* __restrict__ edge_out) {
    __shared__ __align__(16) float zs[NN*ZPAD];        /* z[j][d], padded        */
    __shared__ __align__(16) float vs[NB*NN*ZPAD];     /* v[t][j][d], padded     */
    __shared__ __align__(16) float w1s[NB*BH];         /* [t][j]                 */
    __shared__ __align__(16) float w2t[NB*BH];         /* transposed to [t][j]   */
    __shared__ __align__(16) float b1s[BH];
    __shared__ float wss_s[NB*NB];                     /* [u][t]                 */
    __shared__ float b2s[NB];                          /* b2 + bbs               */

    int b   = blockIdx.x;
    int tid = threadIdx.x;

    /* ---- stage weights ---- */
    for (int i = tid; i < NB*BH; i += 256) {
        w1s[i] = bW1[i];
        int t = i >> 6, j = i & 63;
        w2t[i] = bW2[j*NB + t];
    }
    if (tid < NB*NB) wss_s[tid] = bWs[tid];
    if (tid < BH)    b1s[tid]   = bb1[tid];
    if (tid < NB)    b2s[tid]   = bb2[tid] + bbs[tid];

    /* ---- stage z (vectorized, padded) ---- */
    for (int i = tid; i < NN*8; i += 256) {            /* 320 float4s */
        int n = i >> 3, d4 = i & 7;
        *reinterpret_cast<float4*>(&zs[n*ZPAD + d4*4]) =
            reinterpret_cast<const float4*>(g_z)[(size_t)b*NN*8 + i];
    }
    __syncthreads();

    /* ---- v[t][j][d] = sum_c Wsym[t][c][d] * z[j][c] ---- */
    for (int base = 0; base < NN*8; base += 256) {
        int idx = base + tid;
        if (idx < NN*8) {
            int j = idx >> 3, d4 = idx & 7;
            #pragma unroll
            for (int t = 0; t < NB; t++) {
                float4 acc = make_float4(0.f, 0.f, 0.f, 0.f);
                const float4* W = reinterpret_cast<const float4*>(g_wsym) + t*256 + d4;
                #pragma unroll 8
                for (int c = 0; c < ZDIM; c++) {
                    float zc = zs[j*ZPAD + c];
                    float4 w = W[c*8];
                    acc.x = fmaf(zc, w.x, acc.x);
                    acc.y = fmaf(zc, w.y, acc.y);
                    acc.z = fmaf(zc, w.z, acc.z);
                    acc.w = fmaf(zc, w.w, acc.w);
                }
                *reinterpret_cast<float4*>(&vs[t*NN*ZPAD + j*ZPAD + d4*4]) = acc;
            }
        }
    }
    __syncthreads();

    const int*  eib  = ei       + (size_t)b * EPB * 2;
    float*      outb = edge_out + (size_t)b * EPB * NB;

    for (int p = tid; p < HPAIR; p += 256) {
        int eA = p, eB = p + HPAIR;
        int2 pa = *reinterpret_cast<const int2*>(&eib[2*eA]);
        int2 pb = *reinterpret_cast<const int2*>(&eib[2*eB]);
        int iiA = pa.x - b*NN, jjA = pa.y - b*NN;
        int iiB = pb.x - b*NN, jjB = pb.y - b*NN;

        /* ---- bilinear: bil[t] = z_i . v[t][jj][:] (vectorized) ---- */
        float bilA[NB], bilB[NB];
        {
            float4 ac[NB];
            #pragma unroll
            for (int t = 0; t < NB; t++) ac[t] = make_float4(0.f, 0.f, 0.f, 0.f);
            #pragma unroll
            for (int d4 = 0; d4 < 8; d4++) {
                float4 zi = *reinterpret_cast<const float4*>(&zs[iiA*ZPAD + d4*4]);
                #pragma unroll
                for (int t = 0; t < NB; t++) {
                    float4 v = *reinterpret_cast<const float4*>(&vs[t*NN*ZPAD + jjA*ZPAD + d4*4]);
                    ac[t].x = fmaf(zi.x, v.x, ac[t].x);
                    ac[t].y = fmaf(zi.y, v.y, ac[t].y);
                    ac[t].z = fmaf(zi.z, v.z, ac[t].z);
                    ac[t].w = fmaf(zi.w, v.w, ac[t].w);
                }
            }
            #pragma unroll
            for (int t = 0; t < NB; t++) bilA[t] = (ac[t].x + ac[t].y) + (ac[t].z + ac[t].w);
            #pragma unroll
            for (int t = 0; t < NB; t++) ac[t] = make_float4(0.f, 0.f, 0.f, 0.f);
            #pragma unroll
            for (int d4 = 0; d4 < 8; d4++) {
                float4 zi = *reinterpret_cast<const float4*>(&zs[iiB*ZPAD + d4*4]);
                #pragma unroll
                for (int t = 0; t < NB; t++) {
                    float4 v = *reinterpret_cast<const float4*>(&vs[t*NN*ZPAD + jjB*ZPAD + d4*4]);
                    ac[t].x = fmaf(zi.x, v.x, ac[t].x);
                    ac[t].y = fmaf(zi.y, v.y, ac[t].y);
                    ac[t].z = fmaf(zi.z, v.z, ac[t].z);
                    ac[t].w = fmaf(zi.w, v.w, ac[t].w);
                }
            }
            #pragma unroll
            for (int t = 0; t < NB; t++) bilB[t] = (ac[t].x + ac[t].y) + (ac[t].z + ac[t].w);
        }

        /* ---- skip path into packed accumulators (x half) ---- */
        unsigned long long oA2[NB], oB2[NB];
        #pragma unroll
        for (int t = 0; t < NB; t++) {
            float sa = b2s[t], sb = b2s[t];
            #pragma unroll
            for (int u = 0; u < NB; u++) {
                sa = fmaf(bilA[u], wss_s[u*NB + t], sa);
                sb = fmaf(bilB[u], wss_s[u*NB + t], sb);
            }
            oA2[t] = pk2(sa, 0.f);
            oB2[t] = pk2(sb, 0.f);
        }

        /* ---- packed bil replicas ---- */
        unsigned long long bpA[NB], bpB[NB];
        #pragma unroll
        for (int t = 0; t < NB; t++) {
            bpA[t] = pk2(bilA[t], bilA[t]);
            bpB[t] = pk2(bilB[t], bilB[t]);
        }

        /* ---- hidden layer: 32 j-pairs, packed f32x2 ---- */
        #pragma unroll 4
        for (int jp = 0; jp < BH/2; jp++) {
            unsigned long long b1p = *reinterpret_cast<const unsigned long long*>(&b1s[2*jp]);
            unsigned long long hA = b1p, hB = b1p;
            #pragma unroll
            for (int t = 0; t < NB; t++) {
                unsigned long long w1p =
                    *reinterpret_cast<const unsigned long long*>(&w1s[t*BH + 2*jp]);
                hA = fma2(bpA[t], w1p, hA);
                hB = fma2(bpB[t], w1p, hB);
            }
            { float x, y; upk2(hA, x, y); hA = pk2(fmaxf(x, 0.f), fmaxf(y, 0.f)); }
            { float x, y; upk2(hB, x, y); hB = pk2(fmaxf(x, 0.f), fmaxf(y, 0.f)); }
            #pragma unroll
            for (int t = 0; t < NB; t++) {
                unsigned long long w2p =
                    *reinterpret_cast<const unsigned long long*>(&w2t[t*BH + 2*jp]);
                oA2[t] = fma2(hA, w2p, oA2[t]);
                oB2[t] = fma2(hB, w2p, oB2[t]);
            }
        }

        /* ---- reduce halves, softmax, store ---- */
        float oA[NB], oB[NB];
        #pragma unroll
        for (int t = 0; t < NB; t++) {
            float x, y; upk2(oA2[t], x, y); oA[t] = x + y;
            upk2(oB2[t], x, y);             oB[t] = x + y;
        }
        {
            float m = oA[0];
            #pragma unroll
            for (int t = 1; t < NB; t++) m = fmaxf(m, oA[t]);
            float s = 0.f, e[NB];
            #pragma unroll
            for (int t = 0; t < NB; t++) { e[t] = __expf(oA[t] - m); s += e[t]; }
            float inv = __fdividef(1.f, s);
            #pragma unroll
            for (int t = 0; t < NB; t++) outb[eA*NB + t] = e[t] * inv;
        }
        {
            float m = oB[0];
            #pragma unroll
            for (int t = 1; t < NB; t++) m = fmaxf(m, oB[t]);
            float s = 0.f, e[NB];
            #pragma unroll
            for (int t = 0; t < NB; t++) { e[t] = __expf(oB[t] - m); s += e[t]; }
            float inv = __fdividef(1.f, s);
            #pragma unroll
            for (int t = 0; t < NB; t++) outb[eB*NB + t] = e[t] * inv;
        }
    }
}

/* ------------------------- launch ------------------------- */
extern "C" void kernel_launch(void* const* d_in, const int* in_sizes, int n_in,
                              void* d_out, int out_size) {
    const float* eta  = (const float*)d_in[0];
    const float* gum  = (const float*)d_in[1];
    const float* zn   = (const float*)d_in[2];
    const float* cW1  = (const float*)d_in[3];
    const float* cb1  = (const float*)d_in[4];
    const float* cW2  = (const float*)d_in[5];
    const float* cb2  = (const float*)d_in[6];
    const float* cWs  = (const float*)d_in[7];
    const float* cbs  = (const float*)d_in[8];
    const float* cm   = (const float*)d_in[9];
    const float* cls  = (const float*)d_in[10];
    const float* aW1  = (const float*)d_in[11];
    const float* ab1  = (const float*)d_in[12];
    const float* aW2  = (const float*)d_in[13];
    const float* ab2  = (const float*)d_in[14];
    const float* aWs  = (const float*)d_in[15];
    const float* absk = (const float*)d_in[16];
    const float* bm   = (const float*)d_in[17];
    const float* bW1  = (const float*)d_in[18];
    const float* bb1  = (const float*)d_in[19];
    const float* bW2  = (const float*)d_in[20];
    const float* bb2  = (const float*)d_in[21];
    const float* bWs  = (const float*)d_in[22];
    const float* bbs  = (const float*)d_in[23];
    const int*   ei   = (const int*)  d_in[24];

    float* atom_out = (float*)d_out;                 /* [40960,10]  */
    float* edge_out = atom_out + (size_t)NODES * NA; /* [798720,5]  */

    k_wsym   <<<(NB*ZDIM*ZDIM + 255)/256, 256>>>(bm);
    k_cluster<<<BB, CH>>>(eta, cW1, cb1, cW2, cb2, cWs, cbs);
    k_node   <<<NODES/32, 256>>>(gum, zn, cm, cls, aW1, ab1, aW2, ab2, aWs, absk, atom_out);
    k_edge   <<<BB, 256>>>(ei, bW1, bb1, bW2, bb2, bWs, bbs, edge_out);
}